// round 9
// baseline (speedup 1.0000x reference)
#include <cuda_runtime.h>
#include <cuda_bf16.h>

#define N_NODES 50000
#define N_EDGES 1250000
#define HID 64
#define CDIM 128
#define NTILE 32                                     // K1 GEMM tile
#define N_TILES ((N_NODES + NTILE - 1) / NTILE)
#define GEMM_BLOCKS 148
#define SCAT_BLOCKS 1068
#define TOTAL_BLOCKS (GEMM_BLOCKS + SCAT_BLOCKS)     // 1216 = 152*8
#define TOTAL_ITEMS (16LL * N_EDGES)                 // 20M items
#define CHUNK 4096
#define NUM_CHUNKS ((int)((TOTAL_ITEMS + CHUNK - 1) / CHUNK))   // 4883

#define NT2 64                                       // mlp2 nodes per tile
#define N2_TILES ((N_NODES + NT2 - 1) / NT2)         // 782
#define SW_PAD 68
#define SC_PAD 68

// scratch
__device__ float d_t1[(size_t)N_NODES * HID];
__device__ unsigned int d_chunk_ctr;

// ---------------- f32x2 helpers --------------------------------------------
typedef unsigned long long ull;
__device__ __forceinline__ ull pack2(float lo, float hi) {
    ull r; asm("mov.b64 %0, {%1, %2};" : "=l"(r) : "f"(lo), "f"(hi)); return r;
}
__device__ __forceinline__ void unpack2(ull v, float& lo, float& hi) {
    asm("mov.b64 {%0, %1}, %2;" : "=f"(lo), "=f"(hi) : "l"(v));
}
__device__ __forceinline__ ull fma2(ull a, ull b, ull c) {
    ull d; asm("fma.rn.f32x2 %0, %1, %2, %3;" : "=l"(d) : "l"(a), "l"(b), "l"(c));
    return d;
}

// ---------------------------------------------------------------------------
// one scatter chunk: 4096 consecutive items, 256 threads, 16 iters
// ---------------------------------------------------------------------------
__device__ __forceinline__ void scatter_chunk(const int* __restrict__ row,
                                              const float4* __restrict__ attr4,
                                              float* __restrict__ combined,
                                              long long base, int tid) {
    int lane = tid & 31;
    int g = tid & 15;                       // base is CHUNK-aligned (mult of 16)
    long long idx = base + tid;
    bool full = (base + CHUNK <= TOTAL_ITEMS);

    #pragma unroll 4
    for (int i = 0; i < CHUNK / 256; i++) {
        if (full || idx < TOTAL_ITEMS) {
            int e = (int)(idx >> 4);
            int r;
            if ((lane & 15) == 0) r = __ldg(row + e);
            r = __shfl_sync(0xffffffffu, r, lane & 16);
            float4 v = __ldg(attr4 + idx);
            float* dst = combined + (size_t)r * CDIM + HID + g * 4;
            asm volatile("red.global.add.v4.f32 [%0], {%1, %2, %3, %4};"
                         :: "l"(dst), "f"(v.x), "f"(v.y), "f"(v.z), "f"(v.w)
                         : "memory");
        }
        idx += 256;
    }
}

// ---------------------------------------------------------------------------
// K1: GEMM blocks (first 148) compute t1 = x@W1a + b1 and copy x->combined,
// then join the scatter chunk pool. Scatter blocks pull chunks from the pool.
// ---------------------------------------------------------------------------
__global__ void scatter_gemm_kernel(const int* __restrict__ row,
                                    const float4* __restrict__ attr4,
                                    const float4* __restrict__ x4,
                                    const float* __restrict__ W1,
                                    const float* __restrict__ b1,
                                    float* __restrict__ combined) {
    int tid = threadIdx.x;
    __shared__ int s_chunk;

    if (blockIdx.x < GEMM_BLOCKS) {
        // ---- GEMM branch ----
        extern __shared__ float4 smem4[];
        float*  sW  = (float*)smem4;
        float4* sx4 = smem4 + (HID * HID) / 4;

        for (int i = tid; i < HID * HID; i += 256) sW[i] = W1[i];
        float bj = __ldg(b1 + (tid & 63));
        __syncthreads();

        int g = tid >> 6;
        int j = tid & 63;
        float4* comb4 = (float4*)combined;

        for (int tile = blockIdx.x; tile < N_TILES; tile += GEMM_BLOCKS) {
            int node0 = tile * NTILE;
            for (int i = tid; i < NTILE * 16; i += 256) {
                int n = node0 + (i >> 4), q = i & 15;
                float4 v = make_float4(0.f, 0.f, 0.f, 0.f);
                if (n < N_NODES) {
                    v = __ldg(x4 + (size_t)n * 16 + q);
                    comb4[(size_t)n * 32 + q] = v;
                }
                sx4[i] = v;
            }
            __syncthreads();

            float acc[8];
            #pragma unroll
            for (int n = 0; n < 8; n++) acc[n] = bj;

            const float4* c0 = sx4 + g * 8 * 16;
            #pragma unroll 4
            for (int i4 = 0; i4 < 16; i4++) {
                float w0 = sW[(i4 * 4 + 0) * HID + j];
                float w1 = sW[(i4 * 4 + 1) * HID + j];
                float w2 = sW[(i4 * 4 + 2) * HID + j];
                float w3 = sW[(i4 * 4 + 3) * HID + j];
                #pragma unroll
                for (int n = 0; n < 8; n++) {
                    float4 c = c0[n * 16 + i4];
                    acc[n] = fmaf(c.x, w0, acc[n]);
                    acc[n] = fmaf(c.y, w1, acc[n]);
                    acc[n] = fmaf(c.z, w2, acc[n]);
                    acc[n] = fmaf(c.w, w3, acc[n]);
                }
            }
            #pragma unroll
            for (int n = 0; n < 8; n++) {
                int node = node0 + g * 8 + n;
                if (node < N_NODES) d_t1[(size_t)node * HID + j] = acc[n];
            }
            __syncthreads();
        }
    }

    // ---- chunk pool (all blocks) ----
    for (;;) {
        __syncthreads();
        if (tid == 0) s_chunk = (int)atomicAdd(&d_chunk_ctr, 1u);
        __syncthreads();
        int cid = s_chunk;
        if (cid >= NUM_CHUNKS) break;
        scatter_chunk(row, attr4, combined, (long long)cid * CHUNK, tid);
    }
}

// ---------------------------------------------------------------------------
// K2: out = silu(t1 + agg @ W1b) @ W2 + b2
// One 64-node tile per block. Thread = 8 nodes x 2 features (j, j+32).
// Transposed activations (pair-STS.64 staging), LDS.128 broadcast reads,
// f32x2 FMAs. h overlays agg buffer.
// ---------------------------------------------------------------------------
__global__ void __launch_bounds__(256, 4)
mlp2_kernel(const float* __restrict__ combined,
            const float* __restrict__ W1,
            const float* __restrict__ W2,
            const float* __restrict__ b2,
            float* __restrict__ out) {
    extern __shared__ float smem[];
    float* sW1T = smem;                         // [64][SW_PAD]
    float* sW2T = sW1T + HID * SW_PAD;          // [64][SW_PAD]
    float* scT  = sW2T + HID * SW_PAD;          // [64][SC_PAD] (agg, then h)

    int tid = threadIdx.x;

    for (int i = tid; i < HID * HID; i += 256) {
        int k = i >> 6, j = i & 63;
        sW1T[j * SW_PAD + k] = W1[(HID + k) * HID + j];   // W1b
        sW2T[j * SW_PAD + k] = W2[k * HID + j];
    }

    int g  = tid >> 5;          // node subgroup 0..7 (8 nodes)
    int j  = tid & 31;          // feature a
    int j2 = j + 32;            // feature b
    float b2a = __ldg(b2 + j);
    float b2b = __ldg(b2 + j2);
    ull b2da = pack2(b2a, b2a);
    ull b2db = pack2(b2b, b2b);

    const float4* comb4 = (const float4*)combined;
    int node0 = blockIdx.x * NT2;
    int nb = node0 + g * 8;

    // ---- stage agg transposed, node-pair packed: scT[k][n..n+1] = ull ----
    // item s = (node-pair, q). 8 STS.64 per thread instead of 16 STS.32.
    #pragma unroll
    for (int s = tid; s < (NT2 / 2) * 16; s += 256) {
        int q  = s & 15;
        int n2 = (s >> 4) << 1;
        int nodeA = node0 + n2;
        float4 va = (nodeA < N_NODES)
                      ? __ldg(comb4 + (size_t)nodeA * 32 + 16 + q)
                      : make_float4(0.f, 0.f, 0.f, 0.f);
        float4 vb = (nodeA + 1 < N_NODES)
                      ? __ldg(comb4 + (size_t)(nodeA + 1) * 32 + 16 + q)
                      : make_float4(0.f, 0.f, 0.f, 0.f);
        float* r0 = scT + (q * 4 + 0) * SC_PAD + n2;
        float* r1 = scT + (q * 4 + 1) * SC_PAD + n2;
        float* r2 = scT + (q * 4 + 2) * SC_PAD + n2;
        float* r3 = scT + (q * 4 + 3) * SC_PAD + n2;
        *(ull*)r0 = pack2(va.x, vb.x);
        *(ull*)r1 = pack2(va.y, vb.y);
        *(ull*)r2 = pack2(va.z, vb.z);
        *(ull*)r3 = pack2(va.w, vb.w);
    }

    // ---- t1 prefetch ----
    ull A0[4], A1[4];
    #pragma unroll
    for (int p = 0; p < 4; p++) {
        int n0 = nb + 2 * p;
        float a0 = 0.f, a1 = 0.f, c0 = 0.f, c1 = 0.f;
        if (n0 < N_NODES) {
            a0 = d_t1[(size_t)n0 * HID + j];
            c0 = d_t1[(size_t)n0 * HID + j2];
        }
        if (n0 + 1 < N_NODES) {
            a1 = d_t1[(size_t)(n0 + 1) * HID + j];
            c1 = d_t1[(size_t)(n0 + 1) * HID + j2];
        }
        A0[p] = pack2(a0, a1);
        A1[p] = pack2(c0, c1);
    }
    __syncthreads();

    // ---- layer 1b ----
    {
        const float* wra = sW1T + j  * SW_PAD;
        const float* wrb = sW1T + j2 * SW_PAD;
        #pragma unroll 4
        for (int k4 = 0; k4 < 16; k4++) {
            float4 wa = *(const float4*)(wra + k4 * 4);
            float4 wb = *(const float4*)(wrb + k4 * 4);
            #pragma unroll
            for (int kk = 0; kk < 4; kk++) {
                const float* base = scT + (k4 * 4 + kk) * SC_PAD + g * 8;
                ulonglong2 cA = *(const ulonglong2*)(base);
                ulonglong2 cB = *(const ulonglong2*)(base + 4);
                float wka = (&wa.x)[kk];
                float wkb = (&wb.x)[kk];
                ull wda = pack2(wka, wka);
                ull wdb = pack2(wkb, wkb);
                A0[0] = fma2(cA.x, wda, A0[0]);
                A0[1] = fma2(cA.y, wda, A0[1]);
                A0[2] = fma2(cB.x, wda, A0[2]);
                A0[3] = fma2(cB.y, wda, A0[3]);
                A1[0] = fma2(cA.x, wdb, A1[0]);
                A1[1] = fma2(cA.y, wdb, A1[1]);
                A1[2] = fma2(cB.x, wdb, A1[2]);
                A1[3] = fma2(cB.y, wdb, A1[3]);
            }
        }
    }
    __syncthreads();   // all scT reads complete before overwrite with h

    // ---- SiLU; store h transposed into scT (reuse) ----
    #pragma unroll
    for (int p = 0; p < 4; p++) {
        float a0, a1, c0, c1;
        unpack2(A0[p], a0, a1);
        unpack2(A1[p], c0, c1);
        float h0 = __fdividef(a0, 1.0f + __expf(-a0));
        float h1 = __fdividef(a1, 1.0f + __expf(-a1));
        float h2 = __fdividef(c0, 1.0f + __expf(-c0));
        float h3 = __fdividef(c1, 1.0f + __expf(-c1));
        *(ull*)(scT + j  * SC_PAD + g * 8 + 2 * p) = pack2(h0, h1);
        *(ull*)(scT + j2 * SC_PAD + g * 8 + 2 * p) = pack2(h2, h3);
    }
    __syncthreads();

    // ---- layer 2 ----
    ull B0[4], B1[4];
    #pragma unroll
    for (int p = 0; p < 4; p++) { B0[p] = b2da; B1[p] = b2db; }
    {
        const float* wra = sW2T + j  * SW_PAD;
        const float* wrb = sW2T + j2 * SW_PAD;
        #pragma unroll 4
        for (int k4 = 0; k4 < 16; k4++) {
            float4 wa = *(const float4*)(wra + k4 * 4);
            float4 wb = *(const float4*)(wrb + k4 * 4);
            #pragma unroll
            for (int kk = 0; kk < 4; kk++) {
                const float* base = scT + (k4 * 4 + kk) * SC_PAD + g * 8;
                ulonglong2 cA = *(const ulonglong2*)(base);
                ulonglong2 cB = *(const ulonglong2*)(base + 4);
                float wka = (&wa.x)[kk];
                float wkb = (&wb.x)[kk];
                ull wda = pack2(wka, wka);
                ull wdb = pack2(wkb, wkb);
                B0[0] = fma2(cA.x, wda, B0[0]);
                B0[1] = fma2(cA.y, wda, B0[1]);
                B0[2] = fma2(cB.x, wda, B0[2]);
                B0[3] = fma2(cB.y, wda, B0[3]);
                B1[0] = fma2(cA.x, wdb, B1[0]);
                B1[1] = fma2(cA.y, wdb, B1[1]);
                B1[2] = fma2(cB.x, wdb, B1[2]);
                B1[3] = fma2(cB.y, wdb, B1[3]);
            }
        }
    }
    #pragma unroll
    for (int p = 0; p < 4; p++) {
        float o0, o1, o2, o3;
        unpack2(B0[p], o0, o1);
        unpack2(B1[p], o2, o3);
        int n0 = nb + 2 * p;
        if (n0 < N_NODES) {
            out[(size_t)n0 * HID + j]  = o0;
            out[(size_t)n0 * HID + j2] = o2;
        }
        if (n0 + 1 < N_NODES) {
            out[(size_t)(n0 + 1) * HID + j]  = o1;
            out[(size_t)(n0 + 1) * HID + j2] = o3;
        }
    }
}

// ---------------------------------------------------------------------------
extern "C" void kernel_launch(void* const* d_in, const int* in_sizes, int n_in,
                              void* d_out, int out_size) {
    const int*   edge_index = (const int*)d_in[0];
    const float* edge_attr  = (const float*)d_in[1];
    const float* x          = (const float*)d_in[2];
    const float* W1         = (const float*)d_in[3];
    const float* b1         = (const float*)d_in[4];
    const float* W2         = (const float*)d_in[5];
    const float* b2         = (const float*)d_in[6];

    float* out      = (float*)d_out;
    float* combined = out + (size_t)N_NODES * HID;

    // zero the agg target + chunk counter
    cudaMemsetAsync(combined, 0, (size_t)N_NODES * CDIM * sizeof(float));
    void* ctr_addr = nullptr;
    cudaGetSymbolAddress(&ctr_addr, d_chunk_ctr);
    cudaMemsetAsync(ctr_addr, 0, sizeof(unsigned int));

    // K1: t1 GEMM + dynamically balanced scatter
    {
        int smem = (HID * HID) * 4 + NTILE * 16 * 16;   // 24 KB
        cudaFuncSetAttribute(scatter_gemm_kernel,
                             cudaFuncAttributeMaxDynamicSharedMemorySize, smem);
        scatter_gemm_kernel<<<TOTAL_BLOCKS, 256, smem>>>(
            edge_index, (const float4*)edge_attr, (const float4*)x,
            W1, b1, combined);
    }

    // K2: remaining MLP
    {
        int smem = (2 * HID * SW_PAD + HID * SC_PAD) * (int)sizeof(float);
        cudaFuncSetAttribute(mlp2_kernel,
                             cudaFuncAttributeMaxDynamicSharedMemorySize, smem);
        mlp2_kernel<<<N2_TILES, 256, smem>>>(combined, W1, W2, b2, out);
    }
}

// round 10
// speedup vs baseline: 1.4613x; 1.4613x over previous
#include <cuda_runtime.h>
#include <cuda_bf16.h>
#include <cstdint>

#define N_NODES 50000
#define N_EDGES 1250000
#define HID 64
#define CDIM 128
#define NTILE 32                                     // K1 GEMM tile
#define N_TILES ((N_NODES + NTILE - 1) / NTILE)
#define SCAT_BLOCKS 444
#define GEMM_BLOCKS 148
#define TOTAL_BLOCKS (SCAT_BLOCKS + GEMM_BLOCKS)
#define TOTAL_ITEMS (16LL * N_EDGES)
#define SPLIT_ITEMS 17500000LL

#define MT 128                                       // mlp2 nodes per block
#define M_BLOCKS ((N_NODES + MT - 1) / MT)           // 391
#define A_PAD 76    // act row pad (words): conflict-free A-frag LDS, 16B aligned
#define W_PAD 72    // weight row pad (words): conflict-free B-frag LDS, 16B aligned

// scratch: t1 = x @ W1[0:64] + b1  (fp32, computed free inside K1)
__device__ float d_t1[(size_t)N_NODES * HID];

// ---------------------------------------------------------------------------
// helpers
// ---------------------------------------------------------------------------
__device__ __forceinline__ uint32_t f2tf32(float f) {
    uint32_t r; asm("cvt.rna.tf32.f32 %0, %1;" : "=r"(r) : "f"(f)); return r;
}

__device__ __forceinline__ void mma_tf32(float& d0, float& d1, float& d2, float& d3,
                                         uint32_t a0, uint32_t a1, uint32_t a2, uint32_t a3,
                                         uint32_t b0, uint32_t b1) {
    asm("mma.sync.aligned.m16n8k8.row.col.f32.tf32.tf32.f32 "
        "{%0,%1,%2,%3}, {%4,%5,%6,%7}, {%8,%9}, {%0,%1,%2,%3};"
        : "+f"(d0), "+f"(d1), "+f"(d2), "+f"(d3)
        : "r"(a0), "r"(a1), "r"(a2), "r"(a3), "r"(b0), "r"(b1));
}

// ---------------------------------------------------------------------------
// scatter: sequential edge_attr stream + v4 reductions (R7, proven)
// ---------------------------------------------------------------------------
__device__ __forceinline__ void scatter_range(const int* __restrict__ row,
                                              const float4* __restrict__ attr4,
                                              float* __restrict__ combined,
                                              long long beg, long long end,
                                              long long idx0, long long stride) {
    int lane = threadIdx.x & 31;
    int g = (int)((beg + idx0) & 15);
    long long idx = beg + idx0;

    while (idx - lane + 31 < end) {
        int e = (int)(idx >> 4);
        int r;
        if ((lane & 15) == 0) r = __ldg(row + e);
        r = __shfl_sync(0xffffffffu, r, lane & 16);
        float4 v = __ldg(attr4 + idx);
        float* dst = combined + (size_t)r * CDIM + HID + g * 4;
        asm volatile("red.global.add.v4.f32 [%0], {%1, %2, %3, %4};"
                     :: "l"(dst), "f"(v.x), "f"(v.y), "f"(v.z), "f"(v.w)
                     : "memory");
        idx += stride;
    }
    if (idx < end) {
        int e = (int)(idx >> 4);
        int r = __ldg(row + e);
        float4 v = __ldg(attr4 + idx);
        float* dst = combined + (size_t)r * CDIM + HID + g * 4;
        asm volatile("red.global.add.v4.f32 [%0], {%1, %2, %3, %4};"
                     :: "l"(dst), "f"(v.x), "f"(v.y), "f"(v.z), "f"(v.w)
                     : "memory");
    }
}

// ---------------------------------------------------------------------------
// K1: fused scatter + t1-GEMM (+ combined[:,0:64] = x copy)  (R7, proven)
// ---------------------------------------------------------------------------
__global__ void scatter_gemm_kernel(const int* __restrict__ row,
                                    const float4* __restrict__ attr4,
                                    const float4* __restrict__ x4,
                                    const float* __restrict__ W1,
                                    const float* __restrict__ b1,
                                    float* __restrict__ combined) {
    int tid = threadIdx.x;

    if (blockIdx.x < SCAT_BLOCKS) {
        long long idx0 = (long long)blockIdx.x * 256 + tid;
        scatter_range(row, attr4, combined, 0, SPLIT_ITEMS,
                      idx0, (long long)SCAT_BLOCKS * 256);
        return;
    }

    extern __shared__ float4 smem4[];
    float*  sW  = (float*)smem4;
    float4* sx4 = smem4 + (HID * HID) / 4;

    for (int i = tid; i < HID * HID; i += 256) sW[i] = W1[i];
    float bj = __ldg(b1 + (tid & 63));
    __syncthreads();

    int g = tid >> 6;
    int j = tid & 63;
    int bid = blockIdx.x - SCAT_BLOCKS;
    float4* comb4 = (float4*)combined;

    for (int tile = bid; tile < N_TILES; tile += GEMM_BLOCKS) {
        int node0 = tile * NTILE;
        for (int i = tid; i < NTILE * 16; i += 256) {
            int n = node0 + (i >> 4), q = i & 15;
            float4 v = make_float4(0.f, 0.f, 0.f, 0.f);
            if (n < N_NODES) {
                v = __ldg(x4 + (size_t)n * 16 + q);
                comb4[(size_t)n * 32 + q] = v;
            }
            sx4[i] = v;
        }
        __syncthreads();

        float acc[8];
        #pragma unroll
        for (int n = 0; n < 8; n++) acc[n] = bj;

        const float4* c0 = sx4 + g * 8 * 16;
        #pragma unroll 4
        for (int i4 = 0; i4 < 16; i4++) {
            float w0 = sW[(i4 * 4 + 0) * HID + j];
            float w1 = sW[(i4 * 4 + 1) * HID + j];
            float w2 = sW[(i4 * 4 + 2) * HID + j];
            float w3 = sW[(i4 * 4 + 3) * HID + j];
            #pragma unroll
            for (int n = 0; n < 8; n++) {
                float4 c = c0[n * 16 + i4];
                acc[n] = fmaf(c.x, w0, acc[n]);
                acc[n] = fmaf(c.y, w1, acc[n]);
                acc[n] = fmaf(c.z, w2, acc[n]);
                acc[n] = fmaf(c.w, w3, acc[n]);
            }
        }
        #pragma unroll
        for (int n = 0; n < 8; n++) {
            int node = node0 + g * 8 + n;
            if (node < N_NODES) d_t1[(size_t)node * HID + j] = acc[n];
        }
        __syncthreads();
    }

    long long idx0 = (long long)bid * 256 + tid;
    scatter_range(row, attr4, combined, SPLIT_ITEMS, TOTAL_ITEMS,
                  idx0, (long long)GEMM_BLOCKS * 256);
}

// ---------------------------------------------------------------------------
// K2 (tensor): out = silu(t1 + agg @ W1b) @ W2 + b2   via mma.sync tf32.
// 128-node tile, 8 warps; warp w owns node rows [w*16, w*16+16).
// m16n8k8 frags: lane = 4*g + t  (g = lane>>2, t = lane&3)
//   A (16x8 row):  a0=(g,t) a1=(g+8,t) a2=(g,t+4) a3=(g+8,t+4)
//   B (8x8 col):   b0=(k=t, n=g)  b1=(k=t+4, n=g)
//   D (16x8 f32):  d0=(g,2t) d1=(g,2t+1) d2=(g+8,2t) d3=(g+8,2t+1)
// h overwrites the warp's own agg rows (warp-private; __syncwarp suffices).
// ---------------------------------------------------------------------------
__global__ void __launch_bounds__(256, 2)
mlp2_mma_kernel(const float* __restrict__ combined,
                const float* __restrict__ W1,
                const float* __restrict__ W2,
                const float* __restrict__ b2,
                float* __restrict__ out) {
    extern __shared__ uint32_t smem_u[];
    uint32_t* sW1 = smem_u;                     // [64][W_PAD] tf32 bits
    uint32_t* sW2 = sW1 + HID * W_PAD;          // [64][W_PAD]
    uint32_t* sA  = sW2 + HID * W_PAD;          // [128][A_PAD] agg->h tf32 bits

    int tid  = threadIdx.x;
    int wid  = tid >> 5;
    int lane = tid & 31;
    int g = lane >> 2;
    int t = lane & 3;
    int node0 = blockIdx.x * MT;

    // ---- stage weights (cvt to tf32), rows 16B-aligned ----
    for (int i = tid; i < HID * 16; i += 256) {     // (k, float4-group)
        int k = i >> 4, q = i & 15;
        float4 v1 = __ldg((const float4*)(W1 + (size_t)(HID + k) * HID) + q);
        float4 v2 = __ldg((const float4*)(W2 + (size_t)k * HID) + q);
        uint4 u1 = make_uint4(f2tf32(v1.x), f2tf32(v1.y), f2tf32(v1.z), f2tf32(v1.w));
        uint4 u2 = make_uint4(f2tf32(v2.x), f2tf32(v2.y), f2tf32(v2.z), f2tf32(v2.w));
        *(uint4*)(sW1 + k * W_PAD + q * 4) = u1;
        *(uint4*)(sW2 + k * W_PAD + q * 4) = u2;
    }

    // ---- stage agg (combined[:,64:128]) as tf32, row-major [node][k] ----
    const float4* comb4 = (const float4*)combined;
    for (int i = tid; i < MT * 16; i += 256) {      // (node, float4-group)
        int n = i >> 4, q = i & 15;
        int node = node0 + n;
        float4 v = (node < N_NODES)
                     ? __ldg(comb4 + (size_t)node * 32 + 16 + q)
                     : make_float4(0.f, 0.f, 0.f, 0.f);
        uint4 u = make_uint4(f2tf32(v.x), f2tf32(v.y), f2tf32(v.z), f2tf32(v.w));
        *(uint4*)(sA + n * A_PAD + q * 4) = u;
    }
    __syncthreads();

    int m0 = wid * 16;                 // warp's rows within the tile
    int rowA = node0 + m0 + g;         // global node of frag rows (g)
    int rowB = rowA + 8;               // (g+8)
    bool okA = rowA < N_NODES;
    bool okB = rowB < N_NODES;

    // ---- layer 1: D = t1 + agg @ W1b ----
    float d[8][4];
    #pragma unroll
    for (int nt = 0; nt < 8; nt++) {
        float2 vA = make_float2(0.f, 0.f), vB = make_float2(0.f, 0.f);
        if (okA) vA = *(const float2*)(d_t1 + (size_t)rowA * HID + nt * 8 + 2 * t);
        if (okB) vB = *(const float2*)(d_t1 + (size_t)rowB * HID + nt * 8 + 2 * t);
        d[nt][0] = vA.x; d[nt][1] = vA.y; d[nt][2] = vB.x; d[nt][3] = vB.y;
    }

    #pragma unroll
    for (int kt = 0; kt < 8; kt++) {
        const uint32_t* ar0 = sA + (m0 + g)     * A_PAD + kt * 8;
        const uint32_t* ar1 = sA + (m0 + g + 8) * A_PAD + kt * 8;
        uint32_t a0 = ar0[t];
        uint32_t a1 = ar1[t];
        uint32_t a2 = ar0[t + 4];
        uint32_t a3 = ar1[t + 4];
        #pragma unroll
        for (int nt = 0; nt < 8; nt++) {
            uint32_t b0 = sW1[(kt * 8 + t)     * W_PAD + nt * 8 + g];
            uint32_t b1 = sW1[(kt * 8 + t + 4) * W_PAD + nt * 8 + g];
            mma_tf32(d[nt][0], d[nt][1], d[nt][2], d[nt][3],
                     a0, a1, a2, a3, b0, b1);
        }
    }
    __syncwarp();   // all layer-1 A reads (warp-private rows) done

    // ---- SiLU; store h (tf32) into the warp's own sA rows ----
    #pragma unroll
    for (int nt = 0; nt < 8; nt++) {
        float h0 = __fdividef(d[nt][0], 1.0f + __expf(-d[nt][0]));
        float h1 = __fdividef(d[nt][1], 1.0f + __expf(-d[nt][1]));
        float h2 = __fdividef(d[nt][2], 1.0f + __expf(-d[nt][2]));
        float h3 = __fdividef(d[nt][3], 1.0f + __expf(-d[nt][3]));
        uint32_t* r0 = sA + (m0 + g)     * A_PAD + nt * 8 + 2 * t;
        uint32_t* r1 = sA + (m0 + g + 8) * A_PAD + nt * 8 + 2 * t;
        uint2 u0 = make_uint2(f2tf32(h0), f2tf32(h1));
        uint2 u1 = make_uint2(f2tf32(h2), f2tf32(h3));
        *(uint2*)r0 = u0;
        *(uint2*)r1 = u1;
    }
    __syncwarp();

    // ---- layer 2: D = b2 + h @ W2 ----
    #pragma unroll
    for (int nt = 0; nt < 8; nt++) {
        float2 bb = *(const float2*)(b2 + nt * 8 + 2 * t);
        d[nt][0] = bb.x; d[nt][1] = bb.y; d[nt][2] = bb.x; d[nt][3] = bb.y;
    }

    #pragma unroll
    for (int kt = 0; kt < 8; kt++) {
        const uint32_t* ar0 = sA + (m0 + g)     * A_PAD + kt * 8;
        const uint32_t* ar1 = sA + (m0 + g + 8) * A_PAD + kt * 8;
        uint32_t a0 = ar0[t];
        uint32_t a1 = ar1[t];
        uint32_t a2 = ar0[t + 4];
        uint32_t a3 = ar1[t + 4];
        #pragma unroll
        for (int nt = 0; nt < 8; nt++) {
            uint32_t b0 = sW2[(kt * 8 + t)     * W_PAD + nt * 8 + g];
            uint32_t b1 = sW2[(kt * 8 + t + 4) * W_PAD + nt * 8 + g];
            mma_tf32(d[nt][0], d[nt][1], d[nt][2], d[nt][3],
                     a0, a1, a2, a3, b0, b1);
        }
    }

    // ---- write out ----
    #pragma unroll
    for (int nt = 0; nt < 8; nt++) {
        if (okA) {
            *(float2*)(out + (size_t)rowA * HID + nt * 8 + 2 * t)
                = make_float2(d[nt][0], d[nt][1]);
        }
        if (okB) {
            *(float2*)(out + (size_t)rowB * HID + nt * 8 + 2 * t)
                = make_float2(d[nt][2], d[nt][3]);
        }
    }
}

// ---------------------------------------------------------------------------
extern "C" void kernel_launch(void* const* d_in, const int* in_sizes, int n_in,
                              void* d_out, int out_size) {
    const int*   edge_index = (const int*)d_in[0];
    const float* edge_attr  = (const float*)d_in[1];
    const float* x          = (const float*)d_in[2];
    const float* W1         = (const float*)d_in[3];
    const float* b1         = (const float*)d_in[4];
    const float* W2         = (const float*)d_in[5];
    const float* b2         = (const float*)d_in[6];

    float* out      = (float*)d_out;
    float* combined = out + (size_t)N_NODES * HID;

    cudaMemsetAsync(combined, 0, (size_t)N_NODES * CDIM * sizeof(float));

    // K1: scatter + t1 GEMM + x copy
    {
        int smem = (HID * HID) * 4 + NTILE * 16 * 16;
        cudaFuncSetAttribute(scatter_gemm_kernel,
                             cudaFuncAttributeMaxDynamicSharedMemorySize, smem);
        scatter_gemm_kernel<<<TOTAL_BLOCKS, 256, smem>>>(
            edge_index, (const float4*)edge_attr, (const float4*)x,
            W1, b1, combined);
    }

    // K2: tensor-core MLP
    {
        int smem = (2 * HID * W_PAD + MT * A_PAD) * (int)sizeof(uint32_t);
        cudaFuncSetAttribute(mlp2_mma_kernel,
                             cudaFuncAttributeMaxDynamicSharedMemorySize, smem);
        mlp2_mma_kernel<<<M_BLOCKS, 256, smem>>>(combined, W1, W2, b2, out);
    }
}